// round 3
// baseline (speedup 1.0000x reference)
#include <cuda_runtime.h>
#include <cuda_bf16.h>

#define NN 100000
#define NE 1250000
#define DD 64
#define K_ITERS 5
#define EPSF 1e-8f

// Scratch (device globals — allocation-free). 16B-aligned for float4 access.
__device__ __align__(16) float g_hn[NN * DD];   // normalized tanh features
__device__ float g_deg[NN];       // weighted degree (incl. self loop)
__device__ float g_dis[NN];       // deg^{-1/2}
__device__ float g_nw[NE];        // normalized edge weights
__device__ float g_f[NN];         // propagation state
__device__ float g_agg[NN];       // per-iteration aggregate
__device__ float g_f0[NN];        // relu(mask)

// ---------------------------------------------------------------------------
// K1: h = tanh(x @ W^T + b), then normalize row: hn = h / max(||h||, eps)
// 1 warp per row; lane handles output dims d and d+32.
// ---------------------------------------------------------------------------
__global__ void k_feat(const float* __restrict__ x, const float* __restrict__ W,
                       const float* __restrict__ b) {
    __shared__ float xs[8][DD];
    int warp = threadIdx.x >> 5;
    int lane = threadIdx.x & 31;
    int n = blockIdx.x * 8 + warp;
    if (n >= NN) return;

    xs[warp][lane]      = x[n * DD + lane];
    xs[warp][lane + 32] = x[n * DD + lane + 32];
    __syncwarp();

    float acc0 = b[lane];
    float acc1 = b[lane + 32];
    const float* w0 = W + lane * DD;
    const float* w1 = W + (lane + 32) * DD;
#pragma unroll
    for (int k = 0; k < DD; k++) {
        float xv = xs[warp][k];
        acc0 = fmaf(xv, w0[k], acc0);
        acc1 = fmaf(xv, w1[k], acc1);
    }
    acc0 = tanhf(acc0);
    acc1 = tanhf(acc1);

    float ss = acc0 * acc0 + acc1 * acc1;
#pragma unroll
    for (int o = 16; o; o >>= 1) ss += __shfl_xor_sync(0xffffffffu, ss, o);
    float inv = 1.0f / fmaxf(sqrtf(ss), EPSF);

    g_hn[n * DD + lane]      = acc0 * inv;
    g_hn[n * DD + lane + 32] = acc1 * inv;
}

// ---------------------------------------------------------------------------
// K_init: deg = 1 (self loop), f0 = relu(mask), f = f0
// ---------------------------------------------------------------------------
__global__ void k_init(const float* __restrict__ mask) {
    int n = blockIdx.x * blockDim.x + threadIdx.x;
    if (n < NN) {
        g_deg[n] = 1.0f;
        float f0 = fmaxf(mask[n], 0.0f);
        g_f0[n] = f0;
        g_f[n] = f0;
    }
}

// ---------------------------------------------------------------------------
// K2: edge cosine (relu) + degree accumulation. 16 lanes per edge, float4.
// edge_index is INT32 (jax downcasts int64 without x64 enabled).
// ---------------------------------------------------------------------------
__global__ void k_edge(const int* __restrict__ ei, float* __restrict__ ew_out) {
    int t = blockIdx.x * blockDim.x + threadIdx.x;
    int e = t >> 4;
    int sub = t & 15;
    if (e >= NE) return;

    int s = ei[e];
    int d = ei[NE + e];

    float4 a = *(const float4*)(g_hn + s * DD + sub * 4);
    float4 c = *(const float4*)(g_hn + d * DD + sub * 4);
    float p = a.x * c.x + a.y * c.y + a.z * c.z + a.w * c.w;
#pragma unroll
    for (int o = 8; o; o >>= 1) p += __shfl_xor_sync(0xffffffffu, p, o);

    if (sub == 0) {
        float w = fmaxf(p, 0.0f);
        ew_out[e] = w;
        atomicAdd(&g_deg[d], w);
    }
}

// ---------------------------------------------------------------------------
// K3: dis = rsqrt(max(deg, eps))  (deg >= 1 always here)
// ---------------------------------------------------------------------------
__global__ void k_dis() {
    int n = blockIdx.x * blockDim.x + threadIdx.x;
    if (n < NN) g_dis[n] = rsqrtf(fmaxf(g_deg[n], EPSF));
}

// ---------------------------------------------------------------------------
// K4: nw[e] = dis[src] * w[e] * dis[dst]
// ---------------------------------------------------------------------------
__global__ void k_nw(const int* __restrict__ ei, const float* __restrict__ ew) {
    int e = blockIdx.x * blockDim.x + threadIdx.x;
    if (e >= NE) return;
    int s = ei[e];
    int d = ei[NE + e];
    g_nw[e] = g_dis[s] * ew[e] * g_dis[d];
}

// ---------------------------------------------------------------------------
// Propagation iteration:
//  a) agg[n] = f[n] * dis[n]^2                 (self loop)
//  b) agg[dst] += nw[e] * f[src]               (edge scatter, atomics)
//  c) f[n] = (1-alpha)*agg[n] + alpha*f0[n]
// ---------------------------------------------------------------------------
__global__ void k_prop_self() {
    int n = blockIdx.x * blockDim.x + threadIdx.x;
    if (n < NN) {
        float dis = g_dis[n];
        g_agg[n] = g_f[n] * dis * dis;
    }
}

__global__ void k_prop_edge(const int* __restrict__ ei) {
    int e = blockIdx.x * blockDim.x + threadIdx.x;
    if (e >= NE) return;
    int s = ei[e];
    int d = ei[NE + e];
    atomicAdd(&g_agg[d], g_nw[e] * g_f[s]);
}

__global__ void k_prop_combine(const float* __restrict__ alpha_p) {
    int n = blockIdx.x * blockDim.x + threadIdx.x;
    if (n < NN) {
        float a = *alpha_p;
        g_f[n] = (1.0f - a) * g_agg[n] + a * g_f0[n];
    }
}

__global__ void k_writeout(float* __restrict__ out) {
    int n = blockIdx.x * blockDim.x + threadIdx.x;
    if (n < NN) out[n] = g_f[n];
}

// ---------------------------------------------------------------------------
// Launch
// ---------------------------------------------------------------------------
extern "C" void kernel_launch(void* const* d_in, const int* in_sizes, int n_in,
                              void* d_out, int out_size) {
    const float* x = (const float*)d_in[0];
    const float* mask = (const float*)d_in[1];
    const int* ei = (const int*)d_in[2];
    const float* W = (const float*)d_in[3];
    const float* b = (const float*)d_in[4];
    const float* alpha = (const float*)d_in[5];
    float* out = (float*)d_out;              // [0, NN): f, [NN, NN+NE): edge_weights
    float* ew_out = out + NN;

    const int TB = 256;
    int nodeBlocks = (NN + TB - 1) / TB;
    int edgeBlocks = (NE + TB - 1) / TB;

    k_feat<<<(NN + 7) / 8, 256>>>(x, W, b);
    k_init<<<nodeBlocks, TB>>>(mask);
    k_edge<<<(NE * 16 + TB - 1) / TB, TB>>>(ei, ew_out);
    k_dis<<<nodeBlocks, TB>>>();
    k_nw<<<edgeBlocks, TB>>>(ei, ew_out);

    for (int it = 0; it < K_ITERS; it++) {
        k_prop_self<<<nodeBlocks, TB>>>();
        k_prop_edge<<<edgeBlocks, TB>>>(ei);
        k_prop_combine<<<nodeBlocks, TB>>>(alpha);
    }
    k_writeout<<<nodeBlocks, TB>>>(out);
}